// round 9
// baseline (speedup 1.0000x reference)
#include <cuda_runtime.h>
#include <cstddef>

// ---------------------------------------------------------------------------
// RVQECell: N = 19 qubits (6 inout MSB, 12 workspace, 1 ancilla LSB), B = 32.
// lane l <-> state bit (18 - l).
//
// Plan:
//   K1 build_tables : 54 neuron angle tables, 2^17 x float2 {cos a, sin a}
//   K2 passA        : bitflip + input layer + 3 kernel stages, fused in smem
//                     tiles over the low 13 bits (fixed inout bits = tile id)
//   K3 passB        : 2nd bitflip + 6 output neurons + psi writeback +
//                     partial probability sums (transposed tiles)
//   K4 reduce_probs : deterministic reduction of partials
// ---------------------------------------------------------------------------

#define NB        32
#define NQ        19
#define STATE_SZ  (1u << NQ)         // 524288
#define NTAB      54
#define TAB_SZ    (1u << 17)

__device__ float2 g_tab[(size_t)NTAB * TAB_SZ];      // ~56.6 MB
__device__ float  g_psiA[(size_t)NB * STATE_SZ];     // 64 MB scratch
__device__ float  g_partial[NB * 64 * 64];           // [b][u][v]

// ------------------------- K1: angle tables --------------------------------
__global__ __launch_bounds__(256) void build_tables(
    const float* __restrict__ w_in1, const float* __restrict__ w_in2,
    const float* __restrict__ w_k1,  const float* __restrict__ w_k2,
    const float* __restrict__ w_out1,const float* __restrict__ w_out2)
{
    const int n = blockIdx.y;                       // neuron 0..53
    const int x = blockIdx.x * 256 + threadIdx.x;   // table index 0..2^17-1

    __shared__ float th1[17];
    __shared__ float th2[17 * 17];

    const float *p1, *p2;
    if (n < 12)       { p1 = w_in1  + n * 17;        p2 = w_in2  + n * 289; }
    else if (n < 48)  { int m = n - 12; p1 = w_k1 + m * 17; p2 = w_k2 + m * 289; }
    else              { int m = n - 48; p1 = w_out1 + m * 17; p2 = w_out2 + m * 289; }

    if (threadIdx.x < 17) th1[threadIdx.x] = p1[threadIdx.x];
    for (int i = threadIdx.x; i < 289; i += 256) th2[i] = p2[i];
    __syncthreads();

    // control i <-> bit (16 - i) of x
    float bits[17];
#pragma unroll
    for (int i = 0; i < 17; i++) bits[i] = (float)((x >> (16 - i)) & 1);

    float phi = 1.57079632679489662f;  // BIAS = pi/2
#pragma unroll
    for (int i = 0; i < 17; i++) phi += bits[i] * th1[i];
    // quadratic term: strict upper triangle
    for (int i = 0; i < 16; i++) {
        if (bits[i] != 0.0f) {
            float acc = 0.0f;
            for (int j = i + 1; j < 17; j++) acc += bits[j] * th2[i * 17 + j];
            phi += acc;
        }
    }

    // alpha = arctan2(sin^2 phi, cos^2 phi)  (ORDER=2 -> one iteration)
    // cos(alpha) = c2 / r, sin(alpha) = s2 / r, r = sqrt(c2^2 + s2^2)
    float cp = cosf(phi), sp = sinf(phi);
    float c2 = cp * cp, s2 = sp * sp;
    float r  = rsqrtf(c2 * c2 + s2 * s2);
    g_tab[((size_t)n << 17) | (unsigned)x] = make_float2(c2 * r, s2 * r);
}

// ------------------------- gate helpers (pass A) ---------------------------
// Tile = 8192 amplitudes = inner bits 12..0 (lanes 6..18). Gate on inner bit p.
// Angle index a (11 bits): inner bits [12:p+1] -> a[10:p-1], [p-1:1] -> a[p-2:0].
// Ancilla (bit 0) free -> each angle rotates 2 adjacent pairs -> float2.
__device__ __forceinline__ void gate_neuron(float* sm, int p,
                                            const float2* __restrict__ tab,
                                            int tid)
{
    const int mL = (1 << (p - 1)) - 1;
#pragma unroll
    for (int it = 0; it < 8; it++) {
        const int a  = tid + it * 256;
        float2 cs = __ldg(tab + a);
        const int hi  = a >> (p - 1);
        const int lo  = a & mL;
        const int i00 = (hi << (p + 1)) | (lo << 1);
        const int i10 = i00 | (1 << p);
        float2 v0 = *reinterpret_cast<float2*>(sm + i00);
        float2 v1 = *reinterpret_cast<float2*>(sm + i10);
        float2 n0, n1;
        n0.x = cs.x * v0.x - cs.y * v1.x;
        n0.y = cs.x * v0.y - cs.y * v1.y;
        n1.x = cs.y * v0.x + cs.x * v1.x;
        n1.y = cs.y * v0.y + cs.x * v1.y;
        *reinterpret_cast<float2*>(sm + i00) = n0;
        *reinterpret_cast<float2*>(sm + i10) = n1;
    }
    __syncthreads();
}

__device__ __forceinline__ void gate_uniform(float* sm, int p,
                                             float c, float s, int tid)
{
    const int mL = (1 << (p - 1)) - 1;
#pragma unroll
    for (int it = 0; it < 8; it++) {
        const int a  = tid + it * 256;
        const int hi  = a >> (p - 1);
        const int lo  = a & mL;
        const int i00 = (hi << (p + 1)) | (lo << 1);
        const int i10 = i00 | (1 << p);
        float2 v0 = *reinterpret_cast<float2*>(sm + i00);
        float2 v1 = *reinterpret_cast<float2*>(sm + i10);
        float2 n0, n1;
        n0.x = c * v0.x - s * v1.x;
        n0.y = c * v0.y - s * v1.y;
        n1.x = s * v0.x + c * v1.x;
        n1.y = s * v0.y + c * v1.y;
        *reinterpret_cast<float2*>(sm + i00) = n0;
        *reinterpret_cast<float2*>(sm + i10) = n1;
    }
    __syncthreads();
}

// ------------------------- K2: pass A --------------------------------------
// grid = 32 * 64 blocks; block (b, t): t = inout bits (state bits 18..13).
__global__ __launch_bounds__(256) void passA(
    const float* __restrict__ batch,
    const int*   __restrict__ inputs,
    const float* __restrict__ w_u)
{
    __shared__ float sm[8192];
    const int b   = blockIdx.x >> 6;
    const int t   = blockIdx.x & 63;
    const int tid = threadIdx.x;

    int f6 = 0;
#pragma unroll
    for (int i = 0; i < 6; i++) f6 |= (inputs[b * 6 + i] & 1) << (5 - i);

    // bitflip #1: this tile (post-flip inout bits = t) reads source tile t^f6
    const float* src = batch + ((size_t)b << 19) + ((size_t)(t ^ f6) << 13);
    for (int k = tid; k < 8192; k += 256) sm[k] = src[k];
    __syncthreads();

    // table slice for this tile: inout controls occupy table bits 16..11 -> +t<<11
    const size_t toff = (size_t)(t << 11);

    // input layer: neuron j on workspace lane 6+j -> inner bit p = 12-j
    for (int j = 0; j < 12; j++)
        gate_neuron(sm, 12 - j, g_tab + ((size_t)j << 17) + toff, tid);

    for (int st = 0; st < 3; st++) {
        for (int j = 0; j < 12; j++) {
            float ang = __ldg(&w_u[st * 12 + j]);
            gate_uniform(sm, 12 - j, cosf(ang), sinf(ang), tid);
        }
        for (int j = 0; j < 12; j++)
            gate_neuron(sm, 12 - j,
                        g_tab + ((size_t)(12 + st * 12 + j) << 17) + toff, tid);
    }

    float* dst = g_psiA + ((size_t)b << 19) + ((size_t)t << 13);
    for (int k = tid; k < 8192; k += 256) dst[k] = sm[k];
}

// ------------------------- K3: pass B --------------------------------------
// Transposed tiles: inner = 6 inout bits (v, inner bits 12..7) + state bits 6..0
// (w, inner bits 6..0). Outer u = state bits 12..7 (workspace lanes 6..11).
__global__ __launch_bounds__(256) void passB(
    const int* __restrict__ inputs,
    float* __restrict__ out_psi)
{
    __shared__ float sm[8192];
    const int b   = blockIdx.x >> 6;
    const int u   = blockIdx.x & 63;
    const int tid = threadIdx.x;

    int f6 = 0;
#pragma unroll
    for (int i = 0; i < 6; i++) f6 |= (inputs[b * 6 + i] & 1) << (5 - i);

    // load + bitflip #2 (XOR on inout bits, which are inner here)
    for (int k = tid; k < 8192; k += 256) {
        const int v = k >> 7;
        const int w = k & 127;
        sm[(((v ^ f6) & 63) << 7) | w] =
            g_psiA[((size_t)b << 19) | ((size_t)v << 13) | (unsigned)((u << 7) | w)];
    }
    __syncthreads();

    // output neurons j = 0..5: target inout lane j -> inner bit q = 12-j.
    // table idx = (io5 << 12) | (u << 6) | wk6
    for (int j = 0; j < 6; j++) {
        const float2* tab = g_tab + ((size_t)(48 + j) << 17) + (size_t)(u << 6);
        const int pj = 5 - j;             // removed bit position within v
        const int q  = 12 - j;            // inner bit of target
        const int mL = (1 << pj) - 1;
#pragma unroll
        for (int it = 0; it < 8; it++) {
            const int a   = tid + it * 256;
            const int io5 = a >> 6;       // 5 inout control bits (table 16..12)
            const int wk6 = a & 63;       // workspace lanes 12..17 (table 5..0)
            float2 cs = __ldg(tab + ((io5 << 12) | wk6));
            const int vhi = io5 >> pj;
            const int vlo = io5 & mL;
            const int v0  = (vhi << (pj + 1)) | vlo;   // target bit = 0
            const int i00 = (v0 << 7) | (wk6 << 1);
            const int i10 = i00 | (1 << q);
            float2 a0 = *reinterpret_cast<float2*>(sm + i00);
            float2 a1 = *reinterpret_cast<float2*>(sm + i10);
            float2 n0, n1;
            n0.x = cs.x * a0.x - cs.y * a1.x;
            n0.y = cs.x * a0.y - cs.y * a1.y;
            n1.x = cs.y * a0.x + cs.x * a1.x;
            n1.y = cs.y * a0.y + cs.x * a1.y;
            *reinterpret_cast<float2*>(sm + i00) = n0;
            *reinterpret_cast<float2*>(sm + i10) = n1;
        }
        __syncthreads();
    }

    // write psi back (un-transpose)
    for (int k = tid; k < 8192; k += 256) {
        const int v = k >> 7;
        const int w = k & 127;
        out_psi[((size_t)b << 19) | ((size_t)v << 13) | (unsigned)((u << 7) | w)] = sm[k];
    }

    // partial probs: sum over w (128) for each v (64); deterministic partials
    const int warp = tid >> 5;
    const int lane = tid & 31;
#pragma unroll
    for (int r = 0; r < 8; r++) {
        const int v = warp * 8 + r;
        float x0 = sm[(v << 7) | lane];
        float x1 = sm[(v << 7) | (lane + 32)];
        float x2 = sm[(v << 7) | (lane + 64)];
        float x3 = sm[(v << 7) | (lane + 96)];
        float ssum = x0 * x0 + x1 * x1 + x2 * x2 + x3 * x3;
#pragma unroll
        for (int o = 16; o; o >>= 1) ssum += __shfl_xor_sync(0xffffffffu, ssum, o);
        if (lane == 0) g_partial[(b << 12) | (u << 6) | v] = ssum;
    }
}

// ------------------------- K4: probs reduction -----------------------------
__global__ __launch_bounds__(256) void reduce_probs(float* __restrict__ out_probs)
{
    const int i = blockIdx.x * 256 + threadIdx.x;   // 0..2047 = (b,v)
    if (i >= NB * 64) return;
    const int b = i >> 6;
    const int v = i & 63;
    float s = 0.0f;
    for (int u = 0; u < 64; u++)
        s += g_partial[(b << 12) | (u << 6) | v];
    out_probs[i] = s;
}

// ---------------------------------------------------------------------------
extern "C" void kernel_launch(void* const* d_in, const int* in_sizes, int n_in,
                              void* d_out, int out_size)
{
    const float* batch  = (const float*)d_in[0];
    const float* w_in1  = (const float*)d_in[1];
    const float* w_in2  = (const float*)d_in[2];
    const float* w_u    = (const float*)d_in[3];
    const float* w_k1   = (const float*)d_in[4];
    const float* w_k2   = (const float*)d_in[5];
    const float* w_out1 = (const float*)d_in[6];
    const float* w_out2 = (const float*)d_in[7];
    const int*   inputs = (const int*)d_in[8];

    float* out       = (float*)d_out;
    // output = (probs [32*64], psi [32*2^19]) flattened in order
    float* out_probs = out;
    float* out_psi   = out + (out_size - (int)((size_t)NB * STATE_SZ));

    dim3 gt(TAB_SZ / 256, NTAB);
    build_tables<<<gt, 256>>>(w_in1, w_in2, w_k1, w_k2, w_out1, w_out2);
    passA<<<NB * 64, 256>>>(batch, inputs, w_u);
    passB<<<NB * 64, 256>>>(inputs, out_psi);
    reduce_probs<<<8, 256>>>(out_probs);
}

// round 13
// speedup vs baseline: 1.0026x; 1.0026x over previous
#include <cuda_runtime.h>
#include <cstddef>

// ---------------------------------------------------------------------------
// RVQECell: N = 19 qubits (6 inout MSB, 12 workspace, 1 ancilla LSB), B = 32.
// lane l <-> state bit (18 - l).
//
// Plan:
//   K1 build_tables : 54 neuron angle tables, 2^17 x float2 {cos a, sin a}
//   K2 passA        : bitflip + input layer + 3 kernel stages, fused in smem
//                     tiles over the low 13 bits (fixed inout bits = tile id)
//   K3 passB        : 2nd bitflip + 6 output neurons + psi writeback +
//                     partial probability sums (transposed tiles)
//   K4 reduce_probs : deterministic reduction of partials
// ---------------------------------------------------------------------------

#define NB        32
#define NQ        19
#define STATE_SZ  (1u << NQ)         // 524288
#define NTAB      54
#define TAB_SZ    (1u << 17)

__device__ float2 g_tab[(size_t)NTAB * TAB_SZ];      // ~56.6 MB
__device__ float  g_psiA[(size_t)NB * STATE_SZ];     // 64 MB scratch
__device__ float  g_partial[NB * 64 * 64];           // [b][u][v]

// ------------------------- K1: angle tables --------------------------------
__global__ __launch_bounds__(256) void build_tables(
    const float* __restrict__ w_in1, const float* __restrict__ w_in2,
    const float* __restrict__ w_k1,  const float* __restrict__ w_k2,
    const float* __restrict__ w_out1,const float* __restrict__ w_out2)
{
    const int n = blockIdx.y;                       // neuron 0..53
    const int x = blockIdx.x * 256 + threadIdx.x;   // table index 0..2^17-1

    __shared__ float th1[17];
    __shared__ float th2[17 * 17];

    const float *p1, *p2;
    if (n < 12)       { p1 = w_in1  + n * 17;        p2 = w_in2  + n * 289; }
    else if (n < 48)  { int m = n - 12; p1 = w_k1 + m * 17; p2 = w_k2 + m * 289; }
    else              { int m = n - 48; p1 = w_out1 + m * 17; p2 = w_out2 + m * 289; }

    if (threadIdx.x < 17) th1[threadIdx.x] = p1[threadIdx.x];
    for (int i = threadIdx.x; i < 289; i += 256) th2[i] = p2[i];
    __syncthreads();

    // control i <-> bit (16 - i) of x
    float bits[17];
#pragma unroll
    for (int i = 0; i < 17; i++) bits[i] = (float)((x >> (16 - i)) & 1);

    float phi = 1.57079632679489662f;  // BIAS = pi/2
#pragma unroll
    for (int i = 0; i < 17; i++) phi += bits[i] * th1[i];
    // quadratic term: strict upper triangle
    for (int i = 0; i < 16; i++) {
        if (bits[i] != 0.0f) {
            float acc = 0.0f;
            for (int j = i + 1; j < 17; j++) acc += bits[j] * th2[i * 17 + j];
            phi += acc;
        }
    }

    // alpha = arctan2(sin^2 phi, cos^2 phi)  (ORDER=2 -> one iteration)
    // cos(alpha) = c2 / r, sin(alpha) = s2 / r, r = sqrt(c2^2 + s2^2)
    float cp = cosf(phi), sp = sinf(phi);
    float c2 = cp * cp, s2 = sp * sp;
    float r  = rsqrtf(c2 * c2 + s2 * s2);
    g_tab[((size_t)n << 17) | (unsigned)x] = make_float2(c2 * r, s2 * r);
}

// ------------------------- gate helpers (pass A) ---------------------------
// Tile = 8192 amplitudes = inner bits 12..0 (lanes 6..18). Gate on inner bit p.
// Angle index a (11 bits): inner bits [12:p+1] -> a[10:p-1], [p-1:1] -> a[p-2:0].
// Ancilla (bit 0) free -> each angle rotates 2 adjacent pairs -> float2.
__device__ __forceinline__ void gate_neuron(float* sm, int p,
                                            const float2* __restrict__ tab,
                                            int tid)
{
    const int mL = (1 << (p - 1)) - 1;
#pragma unroll
    for (int it = 0; it < 8; it++) {
        const int a  = tid + it * 256;
        float2 cs = __ldg(tab + a);
        const int hi  = a >> (p - 1);
        const int lo  = a & mL;
        const int i00 = (hi << (p + 1)) | (lo << 1);
        const int i10 = i00 | (1 << p);
        float2 v0 = *reinterpret_cast<float2*>(sm + i00);
        float2 v1 = *reinterpret_cast<float2*>(sm + i10);
        float2 n0, n1;
        n0.x = cs.x * v0.x - cs.y * v1.x;
        n0.y = cs.x * v0.y - cs.y * v1.y;
        n1.x = cs.y * v0.x + cs.x * v1.x;
        n1.y = cs.y * v0.y + cs.x * v1.y;
        *reinterpret_cast<float2*>(sm + i00) = n0;
        *reinterpret_cast<float2*>(sm + i10) = n1;
    }
    __syncthreads();
}

__device__ __forceinline__ void gate_uniform(float* sm, int p,
                                             float c, float s, int tid)
{
    const int mL = (1 << (p - 1)) - 1;
#pragma unroll
    for (int it = 0; it < 8; it++) {
        const int a  = tid + it * 256;
        const int hi  = a >> (p - 1);
        const int lo  = a & mL;
        const int i00 = (hi << (p + 1)) | (lo << 1);
        const int i10 = i00 | (1 << p);
        float2 v0 = *reinterpret_cast<float2*>(sm + i00);
        float2 v1 = *reinterpret_cast<float2*>(sm + i10);
        float2 n0, n1;
        n0.x = c * v0.x - s * v1.x;
        n0.y = c * v0.y - s * v1.y;
        n1.x = s * v0.x + c * v1.x;
        n1.y = s * v0.y + c * v1.y;
        *reinterpret_cast<float2*>(sm + i00) = n0;
        *reinterpret_cast<float2*>(sm + i10) = n1;
    }
    __syncthreads();
}

// ------------------------- K2: pass A --------------------------------------
// grid = 32 * 64 blocks; block (b, t): t = inout bits (state bits 18..13).
__global__ __launch_bounds__(256) void passA(
    const float* __restrict__ batch,
    const int*   __restrict__ inputs,
    const float* __restrict__ w_u)
{
    __shared__ float sm[8192];
    const int b   = blockIdx.x >> 6;
    const int t   = blockIdx.x & 63;
    const int tid = threadIdx.x;

    int f6 = 0;
#pragma unroll
    for (int i = 0; i < 6; i++) f6 |= (inputs[b * 6 + i] & 1) << (5 - i);

    // bitflip #1: this tile (post-flip inout bits = t) reads source tile t^f6
    const float* src = batch + ((size_t)b << 19) + ((size_t)(t ^ f6) << 13);
    for (int k = tid; k < 8192; k += 256) sm[k] = src[k];
    __syncthreads();

    // table slice for this tile: inout controls occupy table bits 16..11 -> +t<<11
    const size_t toff = (size_t)(t << 11);

    // input layer: neuron j on workspace lane 6+j -> inner bit p = 12-j
    for (int j = 0; j < 12; j++)
        gate_neuron(sm, 12 - j, g_tab + ((size_t)j << 17) + toff, tid);

    for (int st = 0; st < 3; st++) {
        for (int j = 0; j < 12; j++) {
            float ang = __ldg(&w_u[st * 12 + j]);
            gate_uniform(sm, 12 - j, cosf(ang), sinf(ang), tid);
        }
        for (int j = 0; j < 12; j++)
            gate_neuron(sm, 12 - j,
                        g_tab + ((size_t)(12 + st * 12 + j) << 17) + toff, tid);
    }

    float* dst = g_psiA + ((size_t)b << 19) + ((size_t)t << 13);
    for (int k = tid; k < 8192; k += 256) dst[k] = sm[k];
}

// ------------------------- K3: pass B --------------------------------------
// Transposed tiles: inner = 6 inout bits (v, inner bits 12..7) + state bits 6..0
// (w, inner bits 6..0). Outer u = state bits 12..7 (workspace lanes 6..11).
__global__ __launch_bounds__(256) void passB(
    const int* __restrict__ inputs,
    float* __restrict__ out_psi)
{
    __shared__ float sm[8192];
    const int b   = blockIdx.x >> 6;
    const int u   = blockIdx.x & 63;
    const int tid = threadIdx.x;

    int f6 = 0;
#pragma unroll
    for (int i = 0; i < 6; i++) f6 |= (inputs[b * 6 + i] & 1) << (5 - i);

    // load + bitflip #2 (XOR on inout bits, which are inner here)
    for (int k = tid; k < 8192; k += 256) {
        const int v = k >> 7;
        const int w = k & 127;
        sm[(((v ^ f6) & 63) << 7) | w] =
            g_psiA[((size_t)b << 19) | ((size_t)v << 13) | (unsigned)((u << 7) | w)];
    }
    __syncthreads();

    // output neurons j = 0..5: target inout lane j -> inner bit q = 12-j.
    // table idx = (io5 << 12) | (u << 6) | wk6
    for (int j = 0; j < 6; j++) {
        const float2* tab = g_tab + ((size_t)(48 + j) << 17) + (size_t)(u << 6);
        const int pj = 5 - j;             // removed bit position within v
        const int q  = 12 - j;            // inner bit of target
        const int mL = (1 << pj) - 1;
#pragma unroll
        for (int it = 0; it < 8; it++) {
            const int a   = tid + it * 256;
            const int io5 = a >> 6;       // 5 inout control bits (table 16..12)
            const int wk6 = a & 63;       // workspace lanes 12..17 (table 5..0)
            float2 cs = __ldg(tab + ((io5 << 12) | wk6));
            const int vhi = io5 >> pj;
            const int vlo = io5 & mL;
            const int v0  = (vhi << (pj + 1)) | vlo;   // target bit = 0
            const int i00 = (v0 << 7) | (wk6 << 1);
            const int i10 = i00 | (1 << q);
            float2 a0 = *reinterpret_cast<float2*>(sm + i00);
            float2 a1 = *reinterpret_cast<float2*>(sm + i10);
            float2 n0, n1;
            n0.x = cs.x * a0.x - cs.y * a1.x;
            n0.y = cs.x * a0.y - cs.y * a1.y;
            n1.x = cs.y * a0.x + cs.x * a1.x;
            n1.y = cs.y * a0.y + cs.x * a1.y;
            *reinterpret_cast<float2*>(sm + i00) = n0;
            *reinterpret_cast<float2*>(sm + i10) = n1;
        }
        __syncthreads();
    }

    // write psi back (un-transpose)
    for (int k = tid; k < 8192; k += 256) {
        const int v = k >> 7;
        const int w = k & 127;
        out_psi[((size_t)b << 19) | ((size_t)v << 13) | (unsigned)((u << 7) | w)] = sm[k];
    }

    // partial probs: sum over w (128) for each v (64); deterministic partials
    const int warp = tid >> 5;
    const int lane = tid & 31;
#pragma unroll
    for (int r = 0; r < 8; r++) {
        const int v = warp * 8 + r;
        float x0 = sm[(v << 7) | lane];
        float x1 = sm[(v << 7) | (lane + 32)];
        float x2 = sm[(v << 7) | (lane + 64)];
        float x3 = sm[(v << 7) | (lane + 96)];
        float ssum = x0 * x0 + x1 * x1 + x2 * x2 + x3 * x3;
#pragma unroll
        for (int o = 16; o; o >>= 1) ssum += __shfl_xor_sync(0xffffffffu, ssum, o);
        if (lane == 0) g_partial[(b << 12) | (u << 6) | v] = ssum;
    }
}

// ------------------------- K4: probs reduction -----------------------------
__global__ __launch_bounds__(256) void reduce_probs(float* __restrict__ out_probs)
{
    const int i = blockIdx.x * 256 + threadIdx.x;   // 0..2047 = (b,v)
    if (i >= NB * 64) return;
    const int b = i >> 6;
    const int v = i & 63;
    float s = 0.0f;
    for (int u = 0; u < 64; u++)
        s += g_partial[(b << 12) | (u << 6) | v];
    out_probs[i] = s;
}

// ---------------------------------------------------------------------------
extern "C" void kernel_launch(void* const* d_in, const int* in_sizes, int n_in,
                              void* d_out, int out_size)
{
    const float* batch  = (const float*)d_in[0];
    const float* w_in1  = (const float*)d_in[1];
    const float* w_in2  = (const float*)d_in[2];
    const float* w_u    = (const float*)d_in[3];
    const float* w_k1   = (const float*)d_in[4];
    const float* w_k2   = (const float*)d_in[5];
    const float* w_out1 = (const float*)d_in[6];
    const float* w_out2 = (const float*)d_in[7];
    const int*   inputs = (const int*)d_in[8];

    float* out       = (float*)d_out;
    // output = (probs [32*64], psi [32*2^19]) flattened in order
    float* out_probs = out;
    float* out_psi   = out + (out_size - (int)((size_t)NB * STATE_SZ));

    dim3 gt(TAB_SZ / 256, NTAB);
    build_tables<<<gt, 256>>>(w_in1, w_in2, w_k1, w_k2, w_out1, w_out2);
    passA<<<NB * 64, 256>>>(batch, inputs, w_u);
    passB<<<NB * 64, 256>>>(inputs, out_psi);
    reduce_probs<<<8, 256>>>(out_probs);
}